// round 11
// baseline (speedup 1.0000x reference)
#include <cuda_runtime.h>
#include <cuda_fp16.h>
#include <cstdint>

// ============================================================================
// Problem constants
// ============================================================================
#define D_IN   1024
#define D_OUT  2048
#define NROWS  8192               // 4 * 2048
#define KBAS   8192               // basis block: k = d*8 + j
#define KTOT   9216               // + silu block: k = 8192 + d
#define KHALF  4608               // split-K: each CTA covers half of K
#define BM     128
#define BN     128
#define BK     64                 // 64 fp16 = 128B rows = SW128 atom
#define NSTEPS (KHALF / BK)       // 72  (multiple of NSTAGES)
#define NSTAGES 3
#define OUTELEM ((size_t)NROWS * D_OUT)   // 16.7M

// SMEM: 3 stages, each = A(16KB) + B(16KB) = 32KB -> 96KB => 2 CTAs/SM
#define SM_STAGE   32768
#define SMEM_TOTAL (NSTAGES * SM_STAGE)         // 98304

// ============================================================================
// Device scratch (static __device__ arrays: sanctioned no-alloc workaround)
// ============================================================================
__device__ __half g_A[(size_t)NROWS * KTOT];   // 151 MB
__device__ __half g_W[(size_t)D_OUT * KTOT];   // 37.7 MB
__device__ float  g_P[2 * OUTELEM];            // 134 MB split-K partials

// ============================================================================
// PTX helpers (base ISA only — harness builds for compute_103, no 'a')
// ============================================================================
__device__ __forceinline__ uint32_t smem_u32(const void* p) {
    uint32_t a;
    asm("{ .reg .u64 t; cvta.to.shared.u64 t, %1; cvt.u32.u64 %0, t; }" : "=r"(a) : "l"(p));
    return a;
}

__device__ __forceinline__ void cp16(uint32_t dst, const void* src) {
    asm volatile("cp.async.cg.shared.global [%0], [%1], 16;" :: "r"(dst), "l"(src));
}
#define CP_COMMIT() asm volatile("cp.async.commit_group;" ::: "memory")
#define CP_WAIT_1() asm volatile("cp.async.wait_group 1;" ::: "memory")

__device__ __forceinline__ void ldsm_x4(uint32_t* r, uint32_t addr) {
    asm volatile("ldmatrix.sync.aligned.m8n8.x4.shared.b16 {%0,%1,%2,%3}, [%4];"
                 : "=r"(r[0]), "=r"(r[1]), "=r"(r[2]), "=r"(r[3]) : "r"(addr));
}

__device__ __forceinline__ void mma_f16(float* c, const uint32_t* a,
                                        uint32_t b0, uint32_t b1) {
    asm volatile(
        "mma.sync.aligned.m16n8k16.row.col.f32.f16.f16.f32 "
        "{%0,%1,%2,%3}, {%4,%5,%6,%7}, {%8,%9}, {%0,%1,%2,%3};"
        : "+f"(c[0]), "+f"(c[1]), "+f"(c[2]), "+f"(c[3])
        : "r"(a[0]), "r"(a[1]), "r"(a[2]), "r"(a[3]), "r"(b0), "r"(b1));
}

// ============================================================================
// Merged prep kernel. Blocks [0, 32768): A-side (one thread per (n,d)):
//   basis block A[n][d*8+j] = B_j(x[n,d]) (exact Cox-de-Boor recursion,
//   uniform grid: all denominators are p*h -> one rcp, zero divides);
//   silu block  A[n][8192+d] = silu(x[n,d]).
// Blocks [32768, 40960): W-side (one thread per (d,o)):
//   W[o][d*8+j] = coef[d][o][j]*ssp[d][o];  W[o][8192+d] = sb[d][o].
// ============================================================================
__global__ void prep_kernel(const float* __restrict__ x, const float* __restrict__ grid,
                            const float* __restrict__ coef, const float* __restrict__ sb,
                            const float* __restrict__ ssp) {
    if (blockIdx.x < 32768u) {
        int idx = blockIdx.x * blockDim.x + threadIdx.x;   // n*1024 + d
        int d = idx & (D_IN - 1);
        int n = idx >> 10;
        float xv = x[idx];
        float gv[12];
#pragma unroll
        for (int m = 0; m < 12; m++) gv[m] = __ldg(grid + d * 12 + m);

        const float invh  = __frcp_rn(gv[1] - gv[0]);
        const float invp[3] = {invh, 0.5f * invh, (1.0f / 3.0f) * invh};

        float B[11];
#pragma unroll
        for (int m = 0; m < 11; m++)
            B[m] = (xv >= gv[m] && xv < gv[m + 1]) ? 1.0f : 0.0f;
#pragma unroll
        for (int p = 1; p <= 3; p++) {
            const float ip = invp[p - 1];
#pragma unroll
            for (int m = 0; m < 11 - p; m++) {
                float left  = (xv - gv[m]) * ip;
                float right = (gv[m + p + 1] - xv) * ip;
                B[m] = left * B[m] + right * B[m + 1];
            }
        }
        __half2 h[4];
#pragma unroll
        for (int j = 0; j < 4; j++)
            h[j] = __floats2half2_rn(B[2 * j], B[2 * j + 1]);
        *reinterpret_cast<uint4*>(g_A + (size_t)n * KTOT + d * 8) =
            *reinterpret_cast<uint4*>(h);
        float s = xv * __frcp_rn(1.0f + __expf(-xv));
        g_A[(size_t)n * KTOT + KBAS + d] = __float2half_rn(s);
    } else {
        int idx = (blockIdx.x - 32768u) * blockDim.x + threadIdx.x;  // d*2048 + o
        int o = idx & (D_OUT - 1);
        int d = idx >> 11;
        size_t doo = (size_t)d * D_OUT + o;
        float ss = ssp[doo];
        float4 c0 = *reinterpret_cast<const float4*>(coef + doo * 8);
        float4 c1 = *reinterpret_cast<const float4*>(coef + doo * 8 + 4);
        __half2 h[4];
        h[0] = __floats2half2_rn(c0.x * ss, c0.y * ss);
        h[1] = __floats2half2_rn(c0.z * ss, c0.w * ss);
        h[2] = __floats2half2_rn(c1.x * ss, c1.y * ss);
        h[3] = __floats2half2_rn(c1.z * ss, c1.w * ss);
        *reinterpret_cast<uint4*>(g_W + (size_t)o * KTOT + d * 8) =
            *reinterpret_cast<uint4*>(h);
        g_W[(size_t)o * KTOT + KBAS + d] = __float2half_rn(sb[doo]);
    }
}

// ============================================================================
// Split-K GEMM: P[kh][8192,2048] = A[:, kh*4608:(kh+1)*4608] @ W_half^T
// (fp16 m16n8k16, f32 acc). Grid (16 n, 64 m, 2 kh) = 2048 CTAs -> 6.92
// waves on 296 slots: tail quantization ~1%. Per-CTA config identical to the
// proven R10 kernel: 256 thr (8 warps 2x4, warp tile 64x32), 3-stage
// cp.async, 96KB smem -> 2 CTAs/SM.
// ============================================================================
__global__ __launch_bounds__(256, 2)
void kan_gemm_kernel() {
    extern __shared__ __align__(128) char smem[];
    const uint32_t sbase = smem_u32(smem);
    const int tid  = threadIdx.x;
    const int lane = tid & 31;
    const int wid  = tid >> 5;          // 0..7
    const int wm   = wid & 1;           // 2 m-bands of 64
    const int wn   = wid >> 1;          // 4 n-bands of 32
    const int n0 = blockIdx.x * BN;     // gridDim.x = 16 (fast axis -> L2 reuse)
    const int m0 = blockIdx.y * BM;
    const int kh = blockIdx.z;          // K half
    const size_t kofs = (size_t)kh * KHALF;

    // ---- fill: A 128 rows x 8 units + B 128 rows x 8 units (16B units) ----
    const int fr = tid >> 3;            // base row 0..31
    const int fu = tid & 7;             // unit within 128B row
    const int fsw = (fu ^ (fr & 7)) << 4;
    const __half* Asrc0 = g_A + (size_t)(m0 + fr) * KTOT + kofs + fu * 8;
    const __half* Bsrc0 = g_W + (size_t)(n0 + fr) * KTOT + kofs + fu * 8;
    auto fill = [&](int s, int k) {
        const __half* Asrc = Asrc0 + (size_t)k * BK;
        const __half* Bsrc = Bsrc0 + (size_t)k * BK;
        uint32_t sA = sbase + s * SM_STAGE + fr * 128 + fsw;
        uint32_t sB = sA + 16384;
#pragma unroll
        for (int i = 0; i < 4; i++)
            cp16(sA + i * 32 * 128, Asrc + (size_t)i * 32 * KTOT);
#pragma unroll
        for (int i = 0; i < 4; i++)
            cp16(sB + i * 32 * 128, Bsrc + (size_t)i * 32 * KTOT);
    };

    fill(0, 0); CP_COMMIT();
    fill(1, 1); CP_COMMIT();

    float acc[4][4][4];
#pragma unroll
    for (int a = 0; a < 4; a++)
#pragma unroll
        for (int j = 0; j < 4; j++)
#pragma unroll
            for (int c = 0; c < 4; c++) acc[a][j][c] = 0.0f;

    // ldmatrix addressing (x4 = one 16x16 fp16 tile)
    const int s7  = lane & 7;
    const int hi  = lane >> 4;
    const int r16 = lane & 15;
    const uint32_t rowA_off = (uint32_t)(wm * 64 + r16) * 128;
    const uint32_t rowB_off = (uint32_t)(wn * 32 + r16) * 128 + 16384;

    int s = 0;                          // stage of step k (manual mod-3)
    int sf = 2;                         // stage of step k+2
    for (int k = 0; k < NSTEPS; k++) {
        CP_WAIT_1();                    // stage s resident
        __syncthreads();                // all warps done reading retiring stage
        if (k + 2 < NSTEPS) fill(sf, k + 2);
        CP_COMMIT();                    // empty group in tail keeps count exact

        const uint32_t sA = sbase + s * SM_STAGE + rowA_off;
        const uint32_t sB = sbase + s * SM_STAGE + rowB_off;
#pragma unroll
        for (int kc = 0; kc < 4; kc++) {
            const uint32_t u = ((uint32_t)((kc * 2 + hi) ^ s7)) << 4;
            uint32_t af[4][4], bf[2][4];
#pragma unroll
            for (int a = 0; a < 4; a++) ldsm_x4(af[a], sA + a * 16 * 128 + u);
#pragma unroll
            for (int nb = 0; nb < 2; nb++) ldsm_x4(bf[nb], sB + nb * 16 * 128 + u);
#pragma unroll
            for (int a = 0; a < 4; a++)
#pragma unroll
                for (int nb = 0; nb < 2; nb++) {
                    mma_f16(acc[a][nb * 2 + 0], af[a], bf[nb][0], bf[nb][2]);
                    mma_f16(acc[a][nb * 2 + 1], af[a], bf[nb][1], bf[nb][3]);
                }
        }
        if (++s == NSTAGES) s = 0;
        if (++sf == NSTAGES) sf = 0;
    }

    // ---- epilogue: regs -> partial plane ----
    float* plane = g_P + (size_t)kh * OUTELEM;
    const int orow0 = m0 + wm * 64 + (lane >> 2);
    const int ocol0 = n0 + wn * 32 + (lane & 3) * 2;
#pragma unroll
    for (int a = 0; a < 4; a++) {
        float* p0 = plane + (size_t)(orow0 + a * 16) * D_OUT + ocol0;
        float* p1 = p0 + 8 * D_OUT;
#pragma unroll
        for (int j = 0; j < 4; j++) {
            *reinterpret_cast<float2*>(p0 + j * 8) = make_float2(acc[a][j][0], acc[a][j][1]);
            *reinterpret_cast<float2*>(p1 + j * 8) = make_float2(acc[a][j][2], acc[a][j][3]);
        }
    }
}

// ============================================================================
// Reduce kernel: out = P0 + P1 (float4 vectorized, fully coalesced)
// ============================================================================
__global__ void reduce_kernel(float* __restrict__ out) {
    size_t i = ((size_t)blockIdx.x * blockDim.x + threadIdx.x) * 4;
    float4 a = *reinterpret_cast<const float4*>(g_P + i);
    float4 b = *reinterpret_cast<const float4*>(g_P + OUTELEM + i);
    float4 r = make_float4(a.x + b.x, a.y + b.y, a.z + b.z, a.w + b.w);
    *reinterpret_cast<float4*>(out + i) = r;
}

// ============================================================================
// Host launch (graph-capturable: kernel launches only)
// ============================================================================
extern "C" void kernel_launch(void* const* d_in, const int* in_sizes, int n_in,
                              void* d_out, int out_size) {
    const float* x    = (const float*)d_in[0];   // (4,2048,1024)
    const float* grid = (const float*)d_in[1];   // (1024,12)
    const float* coef = (const float*)d_in[2];   // (1024,2048,8)
    const float* sb   = (const float*)d_in[3];   // (1024,2048)
    const float* ssp  = (const float*)d_in[4];   // (1024,2048)
    float* out = (float*)d_out;                  // (4,2048,2048)

    prep_kernel<<<32768 + 8192, 256>>>(x, grid, coef, sb, ssp);

    cudaFuncSetAttribute(kan_gemm_kernel,
                         cudaFuncAttributeMaxDynamicSharedMemorySize, SMEM_TOTAL);
    kan_gemm_kernel<<<dim3(D_OUT / BN, NROWS / BM, 2), 256, SMEM_TOTAL>>>();

    reduce_kernel<<<(unsigned)(OUTELEM / 4 / 256), 256>>>(out);
}

// round 12
// speedup vs baseline: 1.0029x; 1.0029x over previous
#include <cuda_runtime.h>
#include <cuda_fp16.h>
#include <cstdint>

// ============================================================================
// Problem constants
// ============================================================================
#define D_IN   1024
#define D_OUT  2048
#define NROWS  8192               // 4 * 2048
#define KBAS   8192               // basis block: k = d*8 + j
#define KTOT   9216               // + silu block: k = 8192 + d
#define KHALF  4608               // split-K: each CTA covers half of K
#define BM     128
#define BN     128
#define BK     64                 // 64 fp16 = 128B rows = SW128 atom
#define NSTEPS (KHALF / BK)       // 72  (multiple of NSTAGES)
#define NSTAGES 3
#define OUTELEM ((size_t)NROWS * D_OUT)   // 16.7M

// SMEM: 3 stages, each = A(16KB) + B(16KB) = 32KB -> 96KB => 2 CTAs/SM
#define SM_STAGE   32768
#define SMEM_TOTAL (NSTAGES * SM_STAGE)         // 98304

// ============================================================================
// Device scratch (static __device__ arrays: sanctioned no-alloc workaround)
// ============================================================================
__device__ __half g_A[(size_t)NROWS * KTOT];   // 151 MB
__device__ __half g_W[(size_t)D_OUT * KTOT];   // 37.7 MB
__device__ float  g_P[2 * OUTELEM];            // 134 MB split-K partials

// ============================================================================
// PTX helpers (base ISA only — harness builds for compute_103, no 'a')
// ============================================================================
__device__ __forceinline__ uint32_t smem_u32(const void* p) {
    uint32_t a;
    asm("{ .reg .u64 t; cvta.to.shared.u64 t, %1; cvt.u32.u64 %0, t; }" : "=r"(a) : "l"(p));
    return a;
}

__device__ __forceinline__ void cp16(uint32_t dst, const void* src) {
    asm volatile("cp.async.cg.shared.global [%0], [%1], 16;" :: "r"(dst), "l"(src));
}
#define CP_COMMIT() asm volatile("cp.async.commit_group;" ::: "memory")
#define CP_WAIT_1() asm volatile("cp.async.wait_group 1;" ::: "memory")

__device__ __forceinline__ void ldsm_x4(uint32_t* r, uint32_t addr) {
    asm volatile("ldmatrix.sync.aligned.m8n8.x4.shared.b16 {%0,%1,%2,%3}, [%4];"
                 : "=r"(r[0]), "=r"(r[1]), "=r"(r[2]), "=r"(r[3]) : "r"(addr));
}

__device__ __forceinline__ void mma_f16(float* c, const uint32_t* a,
                                        uint32_t b0, uint32_t b1) {
    asm volatile(
        "mma.sync.aligned.m16n8k16.row.col.f32.f16.f16.f32 "
        "{%0,%1,%2,%3}, {%4,%5,%6,%7}, {%8,%9}, {%0,%1,%2,%3};"
        : "+f"(c[0]), "+f"(c[1]), "+f"(c[2]), "+f"(c[3])
        : "r"(a[0]), "r"(a[1]), "r"(a[2]), "r"(a[3]), "r"(b0), "r"(b1));
}

// ============================================================================
// Merged prep kernel. Blocks [0, 32768): A-side (one thread per (n,d)):
//   basis block A[n][d*8+j] = B_j(x[n,d]) (exact Cox-de-Boor recursion,
//   uniform grid: all denominators are p*h -> one rcp, zero divides);
//   silu block  A[n][8192+d] = silu(x[n,d]).
// Blocks [32768, 40960): W-side (one thread per (d,o)):
//   W[o][d*8+j] = coef[d][o][j]*ssp[d][o];  W[o][8192+d] = sb[d][o].
// ============================================================================
__global__ void prep_kernel(const float* __restrict__ x, const float* __restrict__ grid,
                            const float* __restrict__ coef, const float* __restrict__ sb,
                            const float* __restrict__ ssp) {
    if (blockIdx.x < 32768u) {
        int idx = blockIdx.x * blockDim.x + threadIdx.x;   // n*1024 + d
        int d = idx & (D_IN - 1);
        int n = idx >> 10;
        float xv = x[idx];
        float gv[12];
#pragma unroll
        for (int m = 0; m < 12; m++) gv[m] = __ldg(grid + d * 12 + m);

        const float invh  = __frcp_rn(gv[1] - gv[0]);
        const float invp[3] = {invh, 0.5f * invh, (1.0f / 3.0f) * invh};

        float B[11];
#pragma unroll
        for (int m = 0; m < 11; m++)
            B[m] = (xv >= gv[m] && xv < gv[m + 1]) ? 1.0f : 0.0f;
#pragma unroll
        for (int p = 1; p <= 3; p++) {
            const float ip = invp[p - 1];
#pragma unroll
            for (int m = 0; m < 11 - p; m++) {
                float left  = (xv - gv[m]) * ip;
                float right = (gv[m + p + 1] - xv) * ip;
                B[m] = left * B[m] + right * B[m + 1];
            }
        }
        __half2 h[4];
#pragma unroll
        for (int j = 0; j < 4; j++)
            h[j] = __floats2half2_rn(B[2 * j], B[2 * j + 1]);
        *reinterpret_cast<uint4*>(g_A + (size_t)n * KTOT + d * 8) =
            *reinterpret_cast<uint4*>(h);
        float s = xv * __frcp_rn(1.0f + __expf(-xv));
        g_A[(size_t)n * KTOT + KBAS + d] = __float2half_rn(s);
    } else {
        int idx = (blockIdx.x - 32768u) * blockDim.x + threadIdx.x;  // d*2048 + o
        int o = idx & (D_OUT - 1);
        int d = idx >> 11;
        size_t doo = (size_t)d * D_OUT + o;
        float ss = ssp[doo];
        float4 c0 = *reinterpret_cast<const float4*>(coef + doo * 8);
        float4 c1 = *reinterpret_cast<const float4*>(coef + doo * 8 + 4);
        __half2 h[4];
        h[0] = __floats2half2_rn(c0.x * ss, c0.y * ss);
        h[1] = __floats2half2_rn(c0.z * ss, c0.w * ss);
        h[2] = __floats2half2_rn(c1.x * ss, c1.y * ss);
        h[3] = __floats2half2_rn(c1.z * ss, c1.w * ss);
        *reinterpret_cast<uint4*>(g_W + (size_t)o * KTOT + d * 8) =
            *reinterpret_cast<uint4*>(h);
        g_W[(size_t)o * KTOT + KBAS + d] = __float2half_rn(sb[doo]);
    }
}

// ============================================================================
// Split-K GEMM: P[kh][8192,2048] = A[:, kh*4608:(kh+1)*4608] @ W_half^T
// (fp16 m16n8k16, f32 acc). Grid (16 n, 64 m, 2 kh) = 2048 CTAs -> 6.92
// waves on 296 slots: tail quantization ~1%. Per-CTA config identical to the
// proven R10 kernel: 256 thr (8 warps 2x4, warp tile 64x32), 3-stage
// cp.async, 96KB smem -> 2 CTAs/SM.
// ============================================================================
__global__ __launch_bounds__(256, 2)
void kan_gemm_kernel() {
    extern __shared__ __align__(128) char smem[];
    const uint32_t sbase = smem_u32(smem);
    const int tid  = threadIdx.x;
    const int lane = tid & 31;
    const int wid  = tid >> 5;          // 0..7
    const int wm   = wid & 1;           // 2 m-bands of 64
    const int wn   = wid >> 1;          // 4 n-bands of 32
    const int n0 = blockIdx.x * BN;     // gridDim.x = 16 (fast axis -> L2 reuse)
    const int m0 = blockIdx.y * BM;
    const int kh = blockIdx.z;          // K half
    const size_t kofs = (size_t)kh * KHALF;

    // ---- fill: A 128 rows x 8 units + B 128 rows x 8 units (16B units) ----
    const int fr = tid >> 3;            // base row 0..31
    const int fu = tid & 7;             // unit within 128B row
    const int fsw = (fu ^ (fr & 7)) << 4;
    const __half* Asrc0 = g_A + (size_t)(m0 + fr) * KTOT + kofs + fu * 8;
    const __half* Bsrc0 = g_W + (size_t)(n0 + fr) * KTOT + kofs + fu * 8;
    auto fill = [&](int s, int k) {
        const __half* Asrc = Asrc0 + (size_t)k * BK;
        const __half* Bsrc = Bsrc0 + (size_t)k * BK;
        uint32_t sA = sbase + s * SM_STAGE + fr * 128 + fsw;
        uint32_t sB = sA + 16384;
#pragma unroll
        for (int i = 0; i < 4; i++)
            cp16(sA + i * 32 * 128, Asrc + (size_t)i * 32 * KTOT);
#pragma unroll
        for (int i = 0; i < 4; i++)
            cp16(sB + i * 32 * 128, Bsrc + (size_t)i * 32 * KTOT);
    };

    fill(0, 0); CP_COMMIT();
    fill(1, 1); CP_COMMIT();

    float acc[4][4][4];
#pragma unroll
    for (int a = 0; a < 4; a++)
#pragma unroll
        for (int j = 0; j < 4; j++)
#pragma unroll
            for (int c = 0; c < 4; c++) acc[a][j][c] = 0.0f;

    // ldmatrix addressing (x4 = one 16x16 fp16 tile)
    const int s7  = lane & 7;
    const int hi  = lane >> 4;
    const int r16 = lane & 15;
    const uint32_t rowA_off = (uint32_t)(wm * 64 + r16) * 128;
    const uint32_t rowB_off = (uint32_t)(wn * 32 + r16) * 128 + 16384;

    int s = 0;                          // stage of step k (manual mod-3)
    int sf = 2;                         // stage of step k+2
    for (int k = 0; k < NSTEPS; k++) {
        CP_WAIT_1();                    // stage s resident
        __syncthreads();                // all warps done reading retiring stage
        if (k + 2 < NSTEPS) fill(sf, k + 2);
        CP_COMMIT();                    // empty group in tail keeps count exact

        const uint32_t sA = sbase + s * SM_STAGE + rowA_off;
        const uint32_t sB = sbase + s * SM_STAGE + rowB_off;
#pragma unroll
        for (int kc = 0; kc < 4; kc++) {
            const uint32_t u = ((uint32_t)((kc * 2 + hi) ^ s7)) << 4;
            uint32_t af[4][4], bf[2][4];
#pragma unroll
            for (int a = 0; a < 4; a++) ldsm_x4(af[a], sA + a * 16 * 128 + u);
#pragma unroll
            for (int nb = 0; nb < 2; nb++) ldsm_x4(bf[nb], sB + nb * 16 * 128 + u);
#pragma unroll
            for (int a = 0; a < 4; a++)
#pragma unroll
                for (int nb = 0; nb < 2; nb++) {
                    mma_f16(acc[a][nb * 2 + 0], af[a], bf[nb][0], bf[nb][2]);
                    mma_f16(acc[a][nb * 2 + 1], af[a], bf[nb][1], bf[nb][3]);
                }
        }
        if (++s == NSTAGES) s = 0;
        if (++sf == NSTAGES) sf = 0;
    }

    // ---- epilogue: regs -> partial plane ----
    float* plane = g_P + (size_t)kh * OUTELEM;
    const int orow0 = m0 + wm * 64 + (lane >> 2);
    const int ocol0 = n0 + wn * 32 + (lane & 3) * 2;
#pragma unroll
    for (int a = 0; a < 4; a++) {
        float* p0 = plane + (size_t)(orow0 + a * 16) * D_OUT + ocol0;
        float* p1 = p0 + 8 * D_OUT;
#pragma unroll
        for (int j = 0; j < 4; j++) {
            *reinterpret_cast<float2*>(p0 + j * 8) = make_float2(acc[a][j][0], acc[a][j][1]);
            *reinterpret_cast<float2*>(p1 + j * 8) = make_float2(acc[a][j][2], acc[a][j][3]);
        }
    }
}

// ============================================================================
// Reduce kernel: out = P0 + P1 (float4 vectorized, fully coalesced)
// ============================================================================
__global__ void reduce_kernel(float* __restrict__ out) {
    size_t i = ((size_t)blockIdx.x * blockDim.x + threadIdx.x) * 4;
    float4 a = *reinterpret_cast<const float4*>(g_P + i);
    float4 b = *reinterpret_cast<const float4*>(g_P + OUTELEM + i);
    float4 r = make_float4(a.x + b.x, a.y + b.y, a.z + b.z, a.w + b.w);
    *reinterpret_cast<float4*>(out + i) = r;
}

// ============================================================================
// Host launch (graph-capturable: kernel launches only)
// ============================================================================
extern "C" void kernel_launch(void* const* d_in, const int* in_sizes, int n_in,
                              void* d_out, int out_size) {
    const float* x    = (const float*)d_in[0];   // (4,2048,1024)
    const float* grid = (const float*)d_in[1];   // (1024,12)
    const float* coef = (const float*)d_in[2];   // (1024,2048,8)
    const float* sb   = (const float*)d_in[3];   // (1024,2048)
    const float* ssp  = (const float*)d_in[4];   // (1024,2048)
    float* out = (float*)d_out;                  // (4,2048,2048)

    prep_kernel<<<32768 + 8192, 256>>>(x, grid, coef, sb, ssp);

    cudaFuncSetAttribute(kan_gemm_kernel,
                         cudaFuncAttributeMaxDynamicSharedMemorySize, SMEM_TOTAL);
    kan_gemm_kernel<<<dim3(D_OUT / BN, NROWS / BM, 2), 256, SMEM_TOTAL>>>();

    reduce_kernel<<<(unsigned)(OUTELEM / 4 / 256), 256>>>(out);
}

// round 15
// speedup vs baseline: 1.0069x; 1.0040x over previous
#include <cuda_runtime.h>
#include <cuda_fp16.h>
#include <cstdint>

// ============================================================================
// Problem constants
// ============================================================================
#define D_IN   1024
#define D_OUT  2048
#define NROWS  8192               // 4 * 2048
#define KBAS   8192               // basis block: k = d*8 + j
#define KTOT   9216               // + silu block: k = 8192 + d
#define KHALF  4608               // split-K: each CTA covers half of K
#define BM     128
#define BN     128
#define BK     64                 // 64 fp16 = 128B rows = SW128 atom
#define NSTEPS (KHALF / BK)       // 72  (multiple of NSTAGES)
#define NSTAGES 3
#define OUTELEM ((size_t)NROWS * D_OUT)   // 16.7M

// Prep grid split
#define PREP_A_BLKS 32768u
#define PREP_W_BLKS 8192u
#define PREP_Z_BLKS 16384u        // zero out: 16.7M floats / (256 thr * 4)

// SMEM: 3 stages, each = A(16KB) + B(16KB) = 32KB -> 96KB => 2 CTAs/SM
#define SM_STAGE   32768
#define SMEM_TOTAL (NSTAGES * SM_STAGE)         // 98304

// ============================================================================
// Device scratch (static __device__ arrays: sanctioned no-alloc workaround)
// ============================================================================
__device__ __half g_A[(size_t)NROWS * KTOT];   // 151 MB
__device__ __half g_W[(size_t)D_OUT * KTOT];   // 37.7 MB

// ============================================================================
// PTX helpers (base ISA only — harness builds for compute_103, no 'a')
// ============================================================================
__device__ __forceinline__ uint32_t smem_u32(const void* p) {
    uint32_t a;
    asm("{ .reg .u64 t; cvta.to.shared.u64 t, %1; cvt.u32.u64 %0, t; }" : "=r"(a) : "l"(p));
    return a;
}

__device__ __forceinline__ void cp16(uint32_t dst, const void* src) {
    asm volatile("cp.async.cg.shared.global [%0], [%1], 16;" :: "r"(dst), "l"(src));
}
#define CP_COMMIT() asm volatile("cp.async.commit_group;" ::: "memory")
#define CP_WAIT_1() asm volatile("cp.async.wait_group 1;" ::: "memory")

__device__ __forceinline__ void ldsm_x4(uint32_t* r, uint32_t addr) {
    asm volatile("ldmatrix.sync.aligned.m8n8.x4.shared.b16 {%0,%1,%2,%3}, [%4];"
                 : "=r"(r[0]), "=r"(r[1]), "=r"(r[2]), "=r"(r[3]) : "r"(addr));
}

__device__ __forceinline__ void mma_f16(float* c, const uint32_t* a,
                                        uint32_t b0, uint32_t b1) {
    asm volatile(
        "mma.sync.aligned.m16n8k16.row.col.f32.f16.f16.f32 "
        "{%0,%1,%2,%3}, {%4,%5,%6,%7}, {%8,%9}, {%0,%1,%2,%3};"
        : "+f"(c[0]), "+f"(c[1]), "+f"(c[2]), "+f"(c[3])
        : "r"(a[0]), "r"(a[1]), "r"(a[2]), "r"(a[3]), "r"(b0), "r"(b1));
}

// red.global.add.f32 (no return value -> REDG, not ATOMG)
__device__ __forceinline__ void red_add(float* p, float v) {
    asm volatile("red.global.add.f32 [%0], %1;" :: "l"(p), "f"(v) : "memory");
}

// ============================================================================
// Merged prep kernel.
// Blocks [0, 32768): A-side (one thread per (n,d)):
//   basis block A[n][d*8+j] = B_j(x[n,d]) (exact Cox-de-Boor recursion,
//   uniform grid: all denominators are p*h -> one rcp, zero divides);
//   silu block  A[n][8192+d] = silu(x[n,d]).
// Blocks [32768, 40960): W-side (one thread per (d,o)):
//   W[o][d*8+j] = coef[d][o][j]*ssp[d][o];  W[o][8192+d] = sb[d][o].
// Blocks [40960, 57344): zero-fill out (GEMM epilogue uses RED.ADD).
// ============================================================================
__global__ void prep_kernel(const float* __restrict__ x, const float* __restrict__ grid,
                            const float* __restrict__ coef, const float* __restrict__ sb,
                            const float* __restrict__ ssp, float* __restrict__ out) {
    if (blockIdx.x < PREP_A_BLKS) {
        int idx = blockIdx.x * blockDim.x + threadIdx.x;   // n*1024 + d
        int d = idx & (D_IN - 1);
        int n = idx >> 10;
        float xv = x[idx];
        float gv[12];
#pragma unroll
        for (int m = 0; m < 12; m++) gv[m] = __ldg(grid + d * 12 + m);

        const float invh  = __frcp_rn(gv[1] - gv[0]);
        const float invp[3] = {invh, 0.5f * invh, (1.0f / 3.0f) * invh};

        float B[11];
#pragma unroll
        for (int m = 0; m < 11; m++)
            B[m] = (xv >= gv[m] && xv < gv[m + 1]) ? 1.0f : 0.0f;
#pragma unroll
        for (int p = 1; p <= 3; p++) {
            const float ip = invp[p - 1];
#pragma unroll
            for (int m = 0; m < 11 - p; m++) {
                float left  = (xv - gv[m]) * ip;
                float right = (gv[m + p + 1] - xv) * ip;
                B[m] = left * B[m] + right * B[m + 1];
            }
        }
        __half2 h[4];
#pragma unroll
        for (int j = 0; j < 4; j++)
            h[j] = __floats2half2_rn(B[2 * j], B[2 * j + 1]);
        *reinterpret_cast<uint4*>(g_A + (size_t)n * KTOT + d * 8) =
            *reinterpret_cast<uint4*>(h);
        float s = xv * __frcp_rn(1.0f + __expf(-xv));
        g_A[(size_t)n * KTOT + KBAS + d] = __float2half_rn(s);
    } else if (blockIdx.x < PREP_A_BLKS + PREP_W_BLKS) {
        int idx = (blockIdx.x - PREP_A_BLKS) * blockDim.x + threadIdx.x;  // d*2048 + o
        int o = idx & (D_OUT - 1);
        int d = idx >> 11;
        size_t doo = (size_t)d * D_OUT + o;
        float ss = ssp[doo];
        float4 c0 = *reinterpret_cast<const float4*>(coef + doo * 8);
        float4 c1 = *reinterpret_cast<const float4*>(coef + doo * 8 + 4);
        __half2 h[4];
        h[0] = __floats2half2_rn(c0.x * ss, c0.y * ss);
        h[1] = __floats2half2_rn(c0.z * ss, c0.w * ss);
        h[2] = __floats2half2_rn(c1.x * ss, c1.y * ss);
        h[3] = __floats2half2_rn(c1.z * ss, c1.w * ss);
        *reinterpret_cast<uint4*>(g_W + (size_t)o * KTOT + d * 8) =
            *reinterpret_cast<uint4*>(h);
        g_W[(size_t)o * KTOT + KBAS + d] = __float2half_rn(sb[doo]);
    } else {
        size_t i = ((size_t)(blockIdx.x - PREP_A_BLKS - PREP_W_BLKS) * blockDim.x
                    + threadIdx.x) * 4;
        *reinterpret_cast<float4*>(out + i) = make_float4(0.f, 0.f, 0.f, 0.f);
    }
}

// ============================================================================
// Split-K GEMM: out += A[:, kh*4608:(kh+1)*4608] @ W_half^T  (RED.ADD combine)
// fp16 m16n8k16, f32 acc. Grid (16 n, 64 m, 2 kh) = 2048 CTAs -> 6.92 waves
// on 296 slots (~1% tail). Exactly-2 float adds per element + zero base =
// commutative = bit-deterministic. Per-CTA config = proven R10: 256 thr
// (8 warps 2x4, warp tile 64x32), 3-stage cp.async, 96KB smem -> 2 CTAs/SM.
// ============================================================================
__global__ __launch_bounds__(256, 2)
void kan_gemm_kernel(float* __restrict__ out) {
    extern __shared__ __align__(128) char smem[];
    const uint32_t sbase = smem_u32(smem);
    const int tid  = threadIdx.x;
    const int lane = tid & 31;
    const int wid  = tid >> 5;          // 0..7
    const int wm   = wid & 1;           // 2 m-bands of 64
    const int wn   = wid >> 1;          // 4 n-bands of 32
    const int n0 = blockIdx.x * BN;     // gridDim.x = 16 (fast axis -> L2 reuse)
    const int m0 = blockIdx.y * BM;
    const size_t kofs = (size_t)blockIdx.z * KHALF;

    // ---- fill: A 128 rows x 8 units + B 128 rows x 8 units (16B units) ----
    const int fr = tid >> 3;            // base row 0..31
    const int fu = tid & 7;             // unit within 128B row
    const int fsw = (fu ^ (fr & 7)) << 4;
    const __half* Asrc0 = g_A + (size_t)(m0 + fr) * KTOT + kofs + fu * 8;
    const __half* Bsrc0 = g_W + (size_t)(n0 + fr) * KTOT + kofs + fu * 8;
    auto fill = [&](int s, int k) {
        const __half* Asrc = Asrc0 + (size_t)k * BK;
        const __half* Bsrc = Bsrc0 + (size_t)k * BK;
        uint32_t sA = sbase + s * SM_STAGE + fr * 128 + fsw;
        uint32_t sB = sA + 16384;
#pragma unroll
        for (int i = 0; i < 4; i++)
            cp16(sA + i * 32 * 128, Asrc + (size_t)i * 32 * KTOT);
#pragma unroll
        for (int i = 0; i < 4; i++)
            cp16(sB + i * 32 * 128, Bsrc + (size_t)i * 32 * KTOT);
    };

    fill(0, 0); CP_COMMIT();
    fill(1, 1); CP_COMMIT();

    float acc[4][4][4];
#pragma unroll
    for (int a = 0; a < 4; a++)
#pragma unroll
        for (int j = 0; j < 4; j++)
#pragma unroll
            for (int c = 0; c < 4; c++) acc[a][j][c] = 0.0f;

    // ldmatrix addressing (x4 = one 16x16 fp16 tile)
    const int s7  = lane & 7;
    const int hi  = lane >> 4;
    const int r16 = lane & 15;
    const uint32_t rowA_off = (uint32_t)(wm * 64 + r16) * 128;
    const uint32_t rowB_off = (uint32_t)(wn * 32 + r16) * 128 + 16384;

    int s = 0;                          // stage of step k (manual mod-3)
    int sf = 2;                         // stage of step k+2
    for (int k = 0; k < NSTEPS; k++) {
        CP_WAIT_1();                    // stage s resident
        __syncthreads();                // all warps done reading retiring stage
        if (k + 2 < NSTEPS) fill(sf, k + 2);
        CP_COMMIT();                    // empty group in tail keeps count exact

        const uint32_t sA = sbase + s * SM_STAGE + rowA_off;
        const uint32_t sB = sbase + s * SM_STAGE + rowB_off;
#pragma unroll
        for (int kc = 0; kc < 4; kc++) {
            const uint32_t u = ((uint32_t)((kc * 2 + hi) ^ s7)) << 4;
            uint32_t af[4][4], bf[2][4];
#pragma unroll
            for (int a = 0; a < 4; a++) ldsm_x4(af[a], sA + a * 16 * 128 + u);
#pragma unroll
            for (int nb = 0; nb < 2; nb++) ldsm_x4(bf[nb], sB + nb * 16 * 128 + u);
#pragma unroll
            for (int a = 0; a < 4; a++)
#pragma unroll
                for (int nb = 0; nb < 2; nb++) {
                    mma_f16(acc[a][nb * 2 + 0], af[a], bf[nb][0], bf[nb][2]);
                    mma_f16(acc[a][nb * 2 + 1], af[a], bf[nb][1], bf[nb][3]);
                }
        }
        if (++s == NSTAGES) s = 0;
        if (++sf == NSTAGES) sf = 0;
    }

    // ---- epilogue: regs -> out via RED.ADD (combine the two K halves) ----
    const int orow0 = m0 + wm * 64 + (lane >> 2);
    const int ocol0 = n0 + wn * 32 + (lane & 3) * 2;
#pragma unroll
    for (int a = 0; a < 4; a++) {
        float* p0 = out + (size_t)(orow0 + a * 16) * D_OUT + ocol0;
        float* p1 = p0 + 8 * D_OUT;
#pragma unroll
        for (int j = 0; j < 4; j++) {
            red_add(p0 + j * 8 + 0, acc[a][j][0]);
            red_add(p0 + j * 8 + 1, acc[a][j][1]);
            red_add(p1 + j * 8 + 0, acc[a][j][2]);
            red_add(p1 + j * 8 + 1, acc[a][j][3]);
        }
    }
}

// ============================================================================
// Host launch (graph-capturable: kernel launches only)
// ============================================================================
extern "C" void kernel_launch(void* const* d_in, const int* in_sizes, int n_in,
                              void* d_out, int out_size) {
    const float* x    = (const float*)d_in[0];   // (4,2048,1024)
    const float* grid = (const float*)d_in[1];   // (1024,12)
    const float* coef = (const float*)d_in[2];   // (1024,2048,8)
    const float* sb   = (const float*)d_in[3];   // (1024,2048)
    const float* ssp  = (const float*)d_in[4];   // (1024,2048)
    float* out = (float*)d_out;                  // (4,2048,2048)

    prep_kernel<<<PREP_A_BLKS + PREP_W_BLKS + PREP_Z_BLKS, 256>>>(
        x, grid, coef, sb, ssp, out);

    cudaFuncSetAttribute(kan_gemm_kernel,
                         cudaFuncAttributeMaxDynamicSharedMemorySize, SMEM_TOTAL);
    kan_gemm_kernel<<<dim3(D_OUT / BN, NROWS / BM, 2), 256, SMEM_TOTAL>>>(out);
}

// round 16
// speedup vs baseline: 1.0371x; 1.0300x over previous
#include <cuda_runtime.h>
#include <cuda_fp16.h>
#include <cstdint>

// ============================================================================
// Problem constants
// ============================================================================
#define D_IN   1024
#define D_OUT  2048
#define NROWS  8192               // 4 * 2048
#define KBAS   8192               // basis block: k = d*8 + j
#define KTOT   9216               // + silu block: k = 8192 + d
#define BM     128
#define BN     64
#define BK     64                 // 64 fp16 = 128B rows = SW128 atom
#define NSTEPS (KTOT / BK)        // 144
#define NSTAGES 3

// SMEM: 3 stages, each = A(16KB) + B(8KB) = 24KB -> 72KB => 3 CTAs/SM
#define SM_STAGE   24576
#define SMEM_TOTAL (NSTAGES * SM_STAGE)         // 73728

// Prep grid split
#define PREP_A_BLKS 16384u        // 2 rows per thread: 4096 row-pairs x 1024 d
#define PREP_W_BLKS 8192u

// ============================================================================
// Device scratch (static __device__ arrays: sanctioned no-alloc workaround)
// ============================================================================
__device__ __half g_A[(size_t)NROWS * KTOT];   // 151 MB
__device__ __half g_W[(size_t)D_OUT * KTOT];   // 37.7 MB

// ============================================================================
// PTX helpers (base ISA only — harness builds for compute_103, no 'a')
// ============================================================================
__device__ __forceinline__ uint32_t smem_u32(const void* p) {
    uint32_t a;
    asm("{ .reg .u64 t; cvta.to.shared.u64 t, %1; cvt.u32.u64 %0, t; }" : "=r"(a) : "l"(p));
    return a;
}

__device__ __forceinline__ void cp16(uint32_t dst, const void* src) {
    asm volatile("cp.async.cg.shared.global [%0], [%1], 16;" :: "r"(dst), "l"(src));
}
#define CP_COMMIT() asm volatile("cp.async.commit_group;" ::: "memory")
#define CP_WAIT_1() asm volatile("cp.async.wait_group 1;" ::: "memory")

__device__ __forceinline__ void ldsm_x4(uint32_t* r, uint32_t addr) {
    asm volatile("ldmatrix.sync.aligned.m8n8.x4.shared.b16 {%0,%1,%2,%3}, [%4];"
                 : "=r"(r[0]), "=r"(r[1]), "=r"(r[2]), "=r"(r[3]) : "r"(addr));
}

__device__ __forceinline__ void mma_f16(float* c, const uint32_t* a,
                                        uint32_t b0, uint32_t b1) {
    asm volatile(
        "mma.sync.aligned.m16n8k16.row.col.f32.f16.f16.f32 "
        "{%0,%1,%2,%3}, {%4,%5,%6,%7}, {%8,%9}, {%0,%1,%2,%3};"
        : "+f"(c[0]), "+f"(c[1]), "+f"(c[2]), "+f"(c[3])
        : "r"(a[0]), "r"(a[1]), "r"(a[2]), "r"(a[3]), "r"(b0), "r"(b1));
}

// ============================================================================
// Merged prep kernel.
// Blocks [0, 16384): A-side, one thread per (row-pair p, d) -> rows 2p, 2p+1.
//   Shares grid knots + reciprocals across both rows (prep is issue-bound).
//   basis block A[n][d*8+j] = B_j(x[n,d]) (exact Cox-de-Boor recursion,
//   uniform grid: all denominators are p*h -> one rcp, zero divides);
//   silu block  A[n][8192+d] = silu(x[n,d]).
// Blocks [16384, 24576): W-side (one thread per (d,o)):
//   W[o][d*8+j] = coef[d][o][j]*ssp[d][o];  W[o][8192+d] = sb[d][o].
// ============================================================================
__global__ void prep_kernel(const float* __restrict__ x, const float* __restrict__ grid,
                            const float* __restrict__ coef, const float* __restrict__ sb,
                            const float* __restrict__ ssp) {
    if (blockIdx.x < PREP_A_BLKS) {
        int idx = blockIdx.x * blockDim.x + threadIdx.x;   // p*1024 + d
        int d = idx & (D_IN - 1);
        int p = idx >> 10;                                 // row pair
        int n0 = p * 2;
        float gv[12];
#pragma unroll
        for (int m = 0; m < 12; m++) gv[m] = __ldg(grid + d * 12 + m);
        const float invh  = __frcp_rn(gv[1] - gv[0]);
        const float invp[3] = {invh, 0.5f * invh, (1.0f / 3.0f) * invh};

#pragma unroll
        for (int r = 0; r < 2; r++) {
            const int n = n0 + r;
            float xv = x[(size_t)n * D_IN + d];
            float B[11];
#pragma unroll
            for (int m = 0; m < 11; m++)
                B[m] = (xv >= gv[m] && xv < gv[m + 1]) ? 1.0f : 0.0f;
#pragma unroll
            for (int q = 1; q <= 3; q++) {
                const float ip = invp[q - 1];
#pragma unroll
                for (int m = 0; m < 11 - q; m++) {
                    float left  = (xv - gv[m]) * ip;
                    float right = (gv[m + q + 1] - xv) * ip;
                    B[m] = left * B[m] + right * B[m + 1];
                }
            }
            __half2 h[4];
#pragma unroll
            for (int j = 0; j < 4; j++)
                h[j] = __floats2half2_rn(B[2 * j], B[2 * j + 1]);
            *reinterpret_cast<uint4*>(g_A + (size_t)n * KTOT + d * 8) =
                *reinterpret_cast<uint4*>(h);
            float s = xv * __frcp_rn(1.0f + __expf(-xv));
            g_A[(size_t)n * KTOT + KBAS + d] = __float2half_rn(s);
        }
    } else {
        int idx = (blockIdx.x - PREP_A_BLKS) * blockDim.x + threadIdx.x;  // d*2048 + o
        int o = idx & (D_OUT - 1);
        int d = idx >> 11;
        size_t doo = (size_t)d * D_OUT + o;
        float ss = ssp[doo];
        float4 c0 = *reinterpret_cast<const float4*>(coef + doo * 8);
        float4 c1 = *reinterpret_cast<const float4*>(coef + doo * 8 + 4);
        __half2 h[4];
        h[0] = __floats2half2_rn(c0.x * ss, c0.y * ss);
        h[1] = __floats2half2_rn(c0.z * ss, c0.w * ss);
        h[2] = __floats2half2_rn(c1.x * ss, c1.y * ss);
        h[3] = __floats2half2_rn(c1.z * ss, c1.w * ss);
        *reinterpret_cast<uint4*>(g_W + (size_t)o * KTOT + d * 8) =
            *reinterpret_cast<uint4*>(h);
        g_W[(size_t)o * KTOT + KBAS + d] = __float2half_rn(sb[doo]);
    }
}

// ============================================================================
// GEMM: out[8192,2048] = A @ W^T  (fp16 m16n8k16, f32 acc)
// 2048 CTAs of 128x64, 256 thr (8 warps 4m x 2n, warp tile 32x32), 3-stage
// cp.async, 72KB smem + <=84 regs -> 3 CTAs/SM (6 warps/SMSP: cross-CTA
// interleaving hides ldsm RAW, barrier skew, and fill bursts).
// ============================================================================
__global__ __launch_bounds__(256, 3)
void kan_gemm_kernel(float* __restrict__ out) {
    extern __shared__ __align__(128) char smem[];
    const uint32_t sbase = smem_u32(smem);
    const int tid  = threadIdx.x;
    const int lane = tid & 31;
    const int wid  = tid >> 5;          // 0..7
    const int wm   = wid >> 1;          // 4 m-bands of 32
    const int wn   = wid & 1;           // 2 n-bands of 32
    const int n0 = blockIdx.x * BN;     // gridDim.x = 32 (fast axis -> L2 reuse)
    const int m0 = blockIdx.y * BM;

    // ---- fill: A 128 rows x 8 units + B 64 rows x 8 units (16B units) ----
    const int fr = tid >> 3;            // base row 0..31
    const int fu = tid & 7;             // unit within 128B row
    const int fsw = (fu ^ (fr & 7)) << 4;
    const __half* Asrc0 = g_A + (size_t)(m0 + fr) * KTOT + fu * 8;
    const __half* Bsrc0 = g_W + (size_t)(n0 + fr) * KTOT + fu * 8;
    auto fill = [&](int s, int k) {
        const __half* Asrc = Asrc0 + (size_t)k * BK;
        const __half* Bsrc = Bsrc0 + (size_t)k * BK;
        uint32_t sA = sbase + s * SM_STAGE + fr * 128 + fsw;
        uint32_t sB = sA + 16384;
#pragma unroll
        for (int i = 0; i < 4; i++)
            cp16(sA + i * 32 * 128, Asrc + (size_t)i * 32 * KTOT);
#pragma unroll
        for (int i = 0; i < 2; i++)
            cp16(sB + i * 32 * 128, Bsrc + (size_t)i * 32 * KTOT);
    };

    fill(0, 0); CP_COMMIT();
    fill(1, 1); CP_COMMIT();

    float acc[2][4][4];
#pragma unroll
    for (int a = 0; a < 2; a++)
#pragma unroll
        for (int j = 0; j < 4; j++)
#pragma unroll
            for (int c = 0; c < 4; c++) acc[a][j][c] = 0.0f;

    // ldmatrix addressing (x4 = one 16x16 fp16 tile)
    const int s7  = lane & 7;
    const int hi  = lane >> 4;
    const int r16 = lane & 15;
    const uint32_t rowA_off = (uint32_t)(wm * 32 + r16) * 128;
    const uint32_t rowB_off = (uint32_t)(wn * 32 + r16) * 128 + 16384;

    int s = 0;                          // stage of step k (manual mod-3)
    int sf = 2;                         // stage of step k+2
    for (int k = 0; k < NSTEPS; k++) {
        CP_WAIT_1();                    // stage s resident
        __syncthreads();                // all warps done reading retiring stage
        if (k + 2 < NSTEPS) fill(sf, k + 2);
        CP_COMMIT();                    // empty group in tail keeps count exact

        const uint32_t sA = sbase + s * SM_STAGE + rowA_off;
        const uint32_t sB = sbase + s * SM_STAGE + rowB_off;
#pragma unroll
        for (int kc = 0; kc < 4; kc++) {
            const uint32_t u = ((uint32_t)((kc * 2 + hi) ^ s7)) << 4;
            uint32_t af[2][4], bf[2][4];
#pragma unroll
            for (int a = 0; a < 2; a++) ldsm_x4(af[a], sA + a * 16 * 128 + u);
#pragma unroll
            for (int nb = 0; nb < 2; nb++) ldsm_x4(bf[nb], sB + nb * 16 * 128 + u);
#pragma unroll
            for (int a = 0; a < 2; a++)
#pragma unroll
                for (int nb = 0; nb < 2; nb++) {
                    mma_f16(acc[a][nb * 2 + 0], af[a], bf[nb][0], bf[nb][2]);
                    mma_f16(acc[a][nb * 2 + 1], af[a], bf[nb][1], bf[nb][3]);
                }
        }
        if (++s == NSTAGES) s = 0;
        if (++sf == NSTAGES) sf = 0;
    }

    // ---- epilogue: regs -> gmem ----
    const int orow0 = m0 + wm * 32 + (lane >> 2);
    const int ocol0 = n0 + wn * 32 + (lane & 3) * 2;
#pragma unroll
    for (int a = 0; a < 2; a++) {
        float* p0 = out + (size_t)(orow0 + a * 16) * D_OUT + ocol0;
        float* p1 = p0 + 8 * D_OUT;
#pragma unroll
        for (int j = 0; j < 4; j++) {
            *reinterpret_cast<float2*>(p0 + j * 8) = make_float2(acc[a][j][0], acc[a][j][1]);
            *reinterpret_cast<float2*>(p1 + j * 8) = make_float2(acc[a][j][2], acc[a][j][3]);
        }
    }
}

// ============================================================================
// Host launch (graph-capturable: kernel launches only)
// ============================================================================
extern "C" void kernel_launch(void* const* d_in, const int* in_sizes, int n_in,
                              void* d_out, int out_size) {
    const float* x    = (const float*)d_in[0];   // (4,2048,1024)
    const float* grid = (const float*)d_in[1];   // (1024,12)
    const float* coef = (const float*)d_in[2];   // (1024,2048,8)
    const float* sb   = (const float*)d_in[3];   // (1024,2048)
    const float* ssp  = (const float*)d_in[4];   // (1024,2048)
    float* out = (float*)d_out;                  // (4,2048,2048)

    prep_kernel<<<PREP_A_BLKS + PREP_W_BLKS, 256>>>(x, grid, coef, sb, ssp);

    cudaFuncSetAttribute(kan_gemm_kernel,
                         cudaFuncAttributeMaxDynamicSharedMemorySize, SMEM_TOTAL);
    kan_gemm_kernel<<<dim3(D_OUT / BN, NROWS / BM), 256, SMEM_TOTAL>>>(out);
}

// round 17
// speedup vs baseline: 1.0646x; 1.0265x over previous
#include <cuda_runtime.h>
#include <cuda_fp16.h>
#include <cstdint>

// ============================================================================
// Problem constants
// ============================================================================
#define D_IN   1024
#define D_OUT  2048
#define NROWS  8192               // 4 * 2048
#define KBAS   8192               // basis block: k = d*8 + j
#define KTOT   9216               // + silu block: k = 8192 + d
#define BM     128
#define BN     128
#define BK     64                 // 64 fp16 = 128B rows = SW128 atom
#define NSTEPS (KTOT / BK)        // 144
#define NSTAGES 3

// SMEM: 3 stages, each = A(16KB) + B(16KB) = 32KB -> 96KB => 2 CTAs/SM
#define SM_STAGE   32768
#define SMEM_TOTAL (NSTAGES * SM_STAGE)         // 98304

// Prep grid split
#define PREP_A_BLKS 16384u        // 2 rows per thread: 4096 row-pairs x 1024 d
#define PREP_W_BLKS 8192u

// ============================================================================
// Device scratch (static __device__ arrays: sanctioned no-alloc workaround)
// ============================================================================
__device__ __half g_A[(size_t)NROWS * KTOT];   // 151 MB
__device__ __half g_W[(size_t)D_OUT * KTOT];   // 37.7 MB

// ============================================================================
// PTX helpers (base ISA only — harness builds for compute_103, no 'a')
// ============================================================================
__device__ __forceinline__ uint32_t smem_u32(const void* p) {
    uint32_t a;
    asm("{ .reg .u64 t; cvta.to.shared.u64 t, %1; cvt.u32.u64 %0, t; }" : "=r"(a) : "l"(p));
    return a;
}

__device__ __forceinline__ void cp16(uint32_t dst, const void* src) {
    asm volatile("cp.async.cg.shared.global [%0], [%1], 16;" :: "r"(dst), "l"(src));
}
#define CP_COMMIT() asm volatile("cp.async.commit_group;" ::: "memory")
#define CP_WAIT_1() asm volatile("cp.async.wait_group 1;" ::: "memory")

__device__ __forceinline__ void ldsm_x4(uint32_t* r, uint32_t addr) {
    asm volatile("ldmatrix.sync.aligned.m8n8.x4.shared.b16 {%0,%1,%2,%3}, [%4];"
                 : "=r"(r[0]), "=r"(r[1]), "=r"(r[2]), "=r"(r[3]) : "r"(addr));
}

__device__ __forceinline__ void mma_f16(float* c, const uint32_t* a,
                                        uint32_t b0, uint32_t b1) {
    asm volatile(
        "mma.sync.aligned.m16n8k16.row.col.f32.f16.f16.f32 "
        "{%0,%1,%2,%3}, {%4,%5,%6,%7}, {%8,%9}, {%0,%1,%2,%3};"
        : "+f"(c[0]), "+f"(c[1]), "+f"(c[2]), "+f"(c[3])
        : "r"(a[0]), "r"(a[1]), "r"(a[2]), "r"(a[3]), "r"(b0), "r"(b1));
}

// ============================================================================
// Merged prep kernel (unchanged from R16 measured config).
// Blocks [0, 16384): A-side, one thread per (row-pair p, d) -> rows 2p, 2p+1.
//   basis block A[n][d*8+j] = B_j(x[n,d]) (exact Cox-de-Boor recursion,
//   uniform grid: all denominators are p*h -> one rcp, zero divides);
//   silu block  A[n][8192+d] = silu(x[n,d]).
// Blocks [16384, 24576): W-side (one thread per (d,o)):
//   W[o][d*8+j] = coef[d][o][j]*ssp[d][o];  W[o][8192+d] = sb[d][o].
// ============================================================================
__global__ void prep_kernel(const float* __restrict__ x, const float* __restrict__ grid,
                            const float* __restrict__ coef, const float* __restrict__ sb,
                            const float* __restrict__ ssp) {
    if (blockIdx.x < PREP_A_BLKS) {
        int idx = blockIdx.x * blockDim.x + threadIdx.x;   // p*1024 + d
        int d = idx & (D_IN - 1);
        int p = idx >> 10;                                 // row pair
        int n0 = p * 2;
        float gv[12];
#pragma unroll
        for (int m = 0; m < 12; m++) gv[m] = __ldg(grid + d * 12 + m);
        const float invh  = __frcp_rn(gv[1] - gv[0]);
        const float invp[3] = {invh, 0.5f * invh, (1.0f / 3.0f) * invh};

#pragma unroll
        for (int r = 0; r < 2; r++) {
            const int n = n0 + r;
            float xv = x[(size_t)n * D_IN + d];
            float B[11];
#pragma unroll
            for (int m = 0; m < 11; m++)
                B[m] = (xv >= gv[m] && xv < gv[m + 1]) ? 1.0f : 0.0f;
#pragma unroll
            for (int q = 1; q <= 3; q++) {
                const float ip = invp[q - 1];
#pragma unroll
                for (int m = 0; m < 11 - q; m++) {
                    float left  = (xv - gv[m]) * ip;
                    float right = (gv[m + q + 1] - xv) * ip;
                    B[m] = left * B[m] + right * B[m + 1];
                }
            }
            __half2 h[4];
#pragma unroll
            for (int j = 0; j < 4; j++)
                h[j] = __floats2half2_rn(B[2 * j], B[2 * j + 1]);
            *reinterpret_cast<uint4*>(g_A + (size_t)n * KTOT + d * 8) =
                *reinterpret_cast<uint4*>(h);
            float s = xv * __frcp_rn(1.0f + __expf(-xv));
            g_A[(size_t)n * KTOT + KBAS + d] = __float2half_rn(s);
        }
    } else {
        int idx = (blockIdx.x - PREP_A_BLKS) * blockDim.x + threadIdx.x;  // d*2048 + o
        int o = idx & (D_OUT - 1);
        int d = idx >> 11;
        size_t doo = (size_t)d * D_OUT + o;
        float ss = ssp[doo];
        float4 c0 = *reinterpret_cast<const float4*>(coef + doo * 8);
        float4 c1 = *reinterpret_cast<const float4*>(coef + doo * 8 + 4);
        __half2 h[4];
        h[0] = __floats2half2_rn(c0.x * ss, c0.y * ss);
        h[1] = __floats2half2_rn(c0.z * ss, c0.w * ss);
        h[2] = __floats2half2_rn(c1.x * ss, c1.y * ss);
        h[3] = __floats2half2_rn(c1.z * ss, c1.w * ss);
        *reinterpret_cast<uint4*>(g_W + (size_t)o * KTOT + d * 8) =
            *reinterpret_cast<uint4*>(h);
        g_W[(size_t)o * KTOT + KBAS + d] = __float2half_rn(sb[doo]);
    }
}

// ============================================================================
// GEMM: out[8192,2048] = A @ W^T  (fp16 m16n8k16, f32 acc)
// 1024 CTAs of 128x128, **128 threads (4 warps, 2x2 grid of 64x64 warp
// tiles)**, 3-stage cp.async, 96KB smem -> 2 CTAs/SM (256 thr/SM => up to
// 256 regs/thread: the 64x64 warp tile fits). Crossbar traffic per CTA-step
// drops 128KB -> 96KB (A read 2x instead of 4x): LDS no longer the binder.
// ============================================================================
__global__ __launch_bounds__(128, 2)
void kan_gemm_kernel(float* __restrict__ out) {
    extern __shared__ __align__(128) char smem[];
    const uint32_t sbase = smem_u32(smem);
    const int tid  = threadIdx.x;
    const int lane = tid & 31;
    const int wid  = tid >> 5;          // 0..3
    const int wm   = wid & 1;           // 2 m-bands of 64
    const int wn   = wid >> 1;          // 2 n-bands of 64
    const int n0 = blockIdx.x * BN;     // gridDim.x = 16 (fast axis -> L2 reuse)
    const int m0 = blockIdx.y * BM;

    // ---- fill: A 128 rows x 8 units + B 128 rows x 8 units (16B units) ----
    // 128 threads: 8 A-rows + 8 B-rows each (stride 16 rows).
    const int fr = tid >> 3;            // base row 0..15
    const int fu = tid & 7;             // unit within 128B row
    const int fsw = (fu ^ (fr & 7)) << 4;   // row&7 invariant under +16
    const __half* Asrc0 = g_A + (size_t)(m0 + fr) * KTOT + fu * 8;
    const __half* Bsrc0 = g_W + (size_t)(n0 + fr) * KTOT + fu * 8;
    auto fill = [&](int s, int k) {
        const __half* Asrc = Asrc0 + (size_t)k * BK;
        const __half* Bsrc = Bsrc0 + (size_t)k * BK;
        uint32_t sA = sbase + s * SM_STAGE + fr * 128 + fsw;
        uint32_t sB = sA + 16384;
#pragma unroll
        for (int i = 0; i < 8; i++)
            cp16(sA + i * 16 * 128, Asrc + (size_t)i * 16 * KTOT);
#pragma unroll
        for (int i = 0; i < 8; i++)
            cp16(sB + i * 16 * 128, Bsrc + (size_t)i * 16 * KTOT);
    };

    fill(0, 0); CP_COMMIT();
    fill(1, 1); CP_COMMIT();

    float acc[4][8][4];
#pragma unroll
    for (int a = 0; a < 4; a++)
#pragma unroll
        for (int j = 0; j < 8; j++)
#pragma unroll
            for (int c = 0; c < 4; c++) acc[a][j][c] = 0.0f;

    // ldmatrix addressing (x4 = one 16x16 fp16 tile)
    const int s7  = lane & 7;
    const int hi  = lane >> 4;
    const int r16 = lane & 15;
    const uint32_t rowA_off = (uint32_t)(wm * 64 + r16) * 128;
    const uint32_t rowB_off = (uint32_t)(wn * 64 + r16) * 128 + 16384;

    int s = 0;                          // stage of step k (manual mod-3)
    int sf = 2;                         // stage of step k+2
    for (int k = 0; k < NSTEPS; k++) {
        CP_WAIT_1();                    // stage s resident
        __syncthreads();                // all warps done reading retiring stage
        if (k + 2 < NSTEPS) fill(sf, k + 2);
        CP_COMMIT();                    // empty group in tail keeps count exact

        const uint32_t sA = sbase + s * SM_STAGE + rowA_off;
        const uint32_t sB = sbase + s * SM_STAGE + rowB_off;
#pragma unroll
        for (int kc = 0; kc < 4; kc++) {
            const uint32_t u = ((uint32_t)((kc * 2 + hi) ^ s7)) << 4;
            uint32_t af[4][4], bf[4][4];
#pragma unroll
            for (int a = 0; a < 4; a++) ldsm_x4(af[a], sA + a * 16 * 128 + u);
#pragma unroll
            for (int nb = 0; nb < 4; nb++) ldsm_x4(bf[nb], sB + nb * 16 * 128 + u);
#pragma unroll
            for (int a = 0; a < 4; a++)
#pragma unroll
                for (int nb = 0; nb < 4; nb++) {
                    mma_f16(acc[a][nb * 2 + 0], af[a], bf[nb][0], bf[nb][2]);
                    mma_f16(acc[a][nb * 2 + 1], af[a], bf[nb][1], bf[nb][3]);
                }
        }
        if (++s == NSTAGES) s = 0;
        if (++sf == NSTAGES) sf = 0;
    }

    // ---- epilogue: regs -> gmem ----
    const int g = lane >> 2;
    const int t = lane & 3;
    const int orow0 = m0 + wm * 64 + g;
    const int ocol0 = n0 + wn * 64 + t * 2;
#pragma unroll
    for (int a = 0; a < 4; a++) {
        float* p0 = out + (size_t)(orow0 + a * 16) * D_OUT + ocol0;
        float* p1 = p0 + 8 * D_OUT;
#pragma unroll
        for (int j = 0; j < 8; j++) {
            *reinterpret_cast<float2*>(p0 + j * 8) = make_float2(acc[a][j][0], acc[a][j][1]);
            *reinterpret_cast<float2*>(p1 + j * 8) = make_float2(acc[a][j][2], acc[a][j][3]);
        }
    }
}

// ============================================================================
// Host launch (graph-capturable: kernel launches only)
// ============================================================================
extern "C" void kernel_launch(void* const* d_in, const int* in_sizes, int n_in,
                              void* d_out, int out_size) {
    const float* x    = (const float*)d_in[0];   // (4,2048,1024)
    const float* grid = (const float*)d_in[1];   // (1024,12)
    const float* coef = (const float*)d_in[2];   // (1024,2048,8)
    const float* sb   = (const float*)d_in[3];   // (1024,2048)
    const float* ssp  = (const float*)d_in[4];   // (1024,2048)
    float* out = (float*)d_out;                  // (4,2048,2048)

    prep_kernel<<<PREP_A_BLKS + PREP_W_BLKS, 256>>>(x, grid, coef, sb, ssp);

    cudaFuncSetAttribute(kan_gemm_kernel,
                         cudaFuncAttributeMaxDynamicSharedMemorySize, SMEM_TOTAL);
    kan_gemm_kernel<<<dim3(D_OUT / BN, NROWS / BM), 128, SMEM_TOTAL>>>(out);
}